// round 12
// baseline (speedup 1.0000x reference)
#include <cuda_runtime.h>

// QWT collapses: filt(x,h) = x * sum(h) (scalar), downsample is linear.
// Every output sub-band = coef * D, D = bicubic stride-2 downsample of image.
// Inputs: image (16,3,512,512) f32, gl/gh/fl/fh (30 f32 each)
// Output: concat of 4 tensors, each (16,12,256,256) f32.
//
// NOTE: filter sums MUST be computed sequentially (k=0..29) — Σgh/Σfl/Σfh are
// cancellation sums ~0 whose fp32 value depends on summation order; keep the
// `#pragma unroll 1` smem-free loop (order-exact, reg-cheap).
//
// Structure (R11): fully smem-free data path. Thread owns 4 consecutive
// output cols of one row: 8 aligned LDG.128 + 8 edge scalars (L1 hits from
// neighbor-lane lines) -> 10 vertical accumulators -> horizontal 4-tap ->
// 16 STG.128 streaming fan-out stores. One early barrier (coef table only).

#define W0 (-0.09375f)
#define W1 ( 0.59375f)
#define W2 ( 0.59375f)
#define W3 (-0.09375f)

// 256 threads/block: 4 output rows x 256 cols of one image.
// Grid: (64 row-groups, 48 images).
__global__ __launch_bounds__(256, 8) void qwt_down_kernel(const float* __restrict__ img,
                                                          const float* __restrict__ gl,
                                                          const float* __restrict__ gh,
                                                          const float* __restrict__ fl,
                                                          const float* __restrict__ fh,
                                                          float* __restrict__ out) {
    __shared__ float sc[16];           // 16 sub-band coefficients

    const int tid  = threadIdx.x;
    const int i0   = blockIdx.x * 4;   // first output row of this block
    const int imgi = blockIdx.y;       // b*3 + c

    // ---- threads 0..15: sequential (order-exact) filter sums + coefs ----
    if (tid < 16) {
        float A = 0.f, B = 0.f, C = 0.f, D = 0.f;
#pragma unroll 1
        for (int k = 0; k < 30; k++) {
            A += gl[k]; B += gh[k]; C += fl[k]; D += fh[k];
        }
        int t = tid >> 2, q = tid & 3;
        float f1 = (t < 2)        ? ((q & 1) ? C : A) : ((q & 1) ? D : B);
        float f2 = ((t & 1) == 0) ? ((q & 2) ? C : A) : ((q & 2) ? D : B);
        sc[tid] = f1 * f2;
    }
    __syncthreads();   // fence sc before use; no other block coupling below

    const int x = tid & 63;                 // col group: outputs 4x..4x+3
    const int y = tid >> 6;                 // output row within block
    const int i = i0 + y;
    const int j0 = 4 * x;

    const float* src = img + (size_t)imgi * 512 * 512;

    const int rb = 2 * i - 1;
    const int cb = 8 * x;                   // aligned source col base
    const int cl = max(0, cb - 1);          // clamped left edge col
    const int cr = min(511, cb + 8);        // clamped right edge col

    // ---- vertical 4-tap pass into 10 register accumulators ----
    float vL = 0.f, vR = 0.f;
    float v0 = 0.f, v1 = 0.f, v2 = 0.f, v3 = 0.f;
    float v4 = 0.f, v5 = 0.f, v6 = 0.f, v7 = 0.f;

#pragma unroll
    for (int r = 0; r < 4; r++) {
        const float w = (r == 0) ? W0 : (r == 1) ? W1 : (r == 2) ? W2 : W3;
        const int rr = min(511, max(0, rb + r));
        const float* row = src + (size_t)rr * 512;
        float4 a0 = *(const float4*)&row[cb];
        float4 a1 = *(const float4*)&row[cb + 4];
        vL += w * row[cl];
        v0 += w * a0.x;  v1 += w * a0.y;  v2 += w * a0.z;  v3 += w * a0.w;
        v4 += w * a1.x;  v5 += w * a1.y;  v6 += w * a1.z;  v7 += w * a1.w;
        vR += w * row[cr];
    }

    // ---- horizontal 4-tap pass: 4 consecutive outputs ----
    float d0 = W0 * vL + W1 * v0 + W2 * v1 + W3 * v2;
    float d1 = W0 * v1 + W1 * v2 + W2 * v3 + W3 * v4;
    float d2 = W0 * v3 + W1 * v4 + W2 * v5 + W3 * v6;
    float d3 = W0 * v5 + W1 * v6 + W2 * v7 + W3 * vR;

    const int b = imgi / 3;
    const int c = imgi % 3;
    // out[t][b, q*3+c, i, j]  with tensor size 16*12*256*256
    float* p = out + ((size_t)(b * 12 + c) * 256 + i) * 256 + j0;

#pragma unroll
    for (int t = 0; t < 4; t++) {
        float* pt = p + (size_t)t * (16 * 12 * 256 * 256);
#pragma unroll
        for (int q = 0; q < 4; q++) {
            float s = sc[t * 4 + q];
            float4 o = make_float4(s * d0, s * d1, s * d2, s * d3);
            __stcs((float4*)&pt[q * (3 * 256 * 256)], o);
        }
    }
}

extern "C" void kernel_launch(void* const* d_in, const int* in_sizes, int n_in,
                              void* d_out, int out_size) {
    const float* image = (const float*)d_in[0];
    const float* gl    = (const float*)d_in[1];
    const float* gh    = (const float*)d_in[2];
    const float* fl    = (const float*)d_in[3];
    const float* fh    = (const float*)d_in[4];
    float* out = (float*)d_out;

    dim3 block(256, 1, 1);
    dim3 grid(64, 48, 1);
    qwt_down_kernel<<<grid, block>>>(image, gl, gh, fl, fh, out);
}

// round 14
// speedup vs baseline: 1.0308x; 1.0308x over previous
#include <cuda_runtime.h>

// QWT collapses: filt(x,h) = x * sum(h) (scalar), downsample is linear.
// Every output sub-band = coef * D, D = bicubic stride-2 downsample of image.
// Inputs: image (16,3,512,512) f32, gl/gh/fl/fh (30 f32 each)
// Output: concat of 4 tensors, each (16,12,256,256) f32.
//
// NOTE: filter sums MUST be computed sequentially (k=0..29) — Σgh/Σfl/Σfh are
// cancellation sums ~0 whose fp32 value depends on summation order; keep the
// `#pragma unroll 1` loop (order-exact, reg-cheap).
//
// R13 structure (rerun; previous attempt hit a container infra failure):
// shuffle-based, zero data-path smem/barriers.
//  - lane l: coalesced float4 load at source col 4l (warp = 512B span),
//    vertical 4-tap into v0..v3
//  - neighbor v values via __shfl_up/__shfl_down; warp-edge columns from two
//    warp-uniform broadcast scalar loads
//  - lane owns output cols {2l, 2l+1}: 16 float2 streaming fan-out stores

#define W0 (-0.09375f)
#define W1 ( 0.59375f)
#define W2 ( 0.59375f)
#define W3 (-0.09375f)

// 256 threads = 8 warps. Warp handles 64 output cols of one row.
// Block: 2 output rows x 256 cols. Grid: (128 row-pairs, 48 images).
__global__ __launch_bounds__(256, 8) void qwt_down_kernel(const float* __restrict__ img,
                                                          const float* __restrict__ gl,
                                                          const float* __restrict__ gh,
                                                          const float* __restrict__ fl,
                                                          const float* __restrict__ fh,
                                                          float* __restrict__ out) {
    __shared__ float sc[16];           // 16 sub-band coefficients

    const int tid = threadIdx.x;

    // ---- threads 0..15: sequential (order-exact) filter sums + coefs ----
    if (tid < 16) {
        float A = 0.f, B = 0.f, C = 0.f, D = 0.f;
#pragma unroll 1
        for (int k = 0; k < 30; k++) {
            A += gl[k]; B += gh[k]; C += fl[k]; D += fh[k];
        }
        int t = tid >> 2, q = tid & 3;
        float f1 = (t < 2)        ? ((q & 1) ? C : A) : ((q & 1) ? D : B);
        float f2 = ((t & 1) == 0) ? ((q & 2) ? C : A) : ((q & 2) ? D : B);
        sc[tid] = f1 * f2;
    }
    __syncthreads();   // fence sc; only barrier in the kernel

    const int wrp  = tid >> 5;             // warp 0..7
    const int lane = tid & 31;
    const int y    = wrp >> 2;             // row within block (0..1)
    const int jb   = (wrp & 3) * 64;       // warp's output col base
    const int i    = blockIdx.x * 2 + y;   // output row
    const int imgi = blockIdx.y;           // b*3 + c

    const float* src = img + (size_t)imgi * 512 * 512;

    const int rb   = 2 * i - 1;
    const int cb   = 2 * jb;               // warp's source col base (0/128/256/384)
    const int c0   = cb + 4 * lane;        // lane's float4 col (coalesced)
    const int colL = max(0, cb - 1);       // warp-uniform left edge col
    const int colR = min(511, cb + 128);   // warp-uniform right edge col

    // ---- vertical 4-tap pass (coalesced float4 + 2 broadcast edge cols) ----
    float v0 = 0.f, v1 = 0.f, v2 = 0.f, v3 = 0.f;
    float vEL = 0.f, vER = 0.f;
#pragma unroll
    for (int r = 0; r < 4; r++) {
        const float w = (r == 0) ? W0 : (r == 1) ? W1 : (r == 2) ? W2 : W3;
        const int rr = min(511, max(0, rb + r));
        const float* row = src + (size_t)rr * 512;
        float4 a = *(const float4*)&row[c0];
        v0 += w * a.x;  v1 += w * a.y;  v2 += w * a.z;  v3 += w * a.w;
        vEL += w * row[colL];
        vER += w * row[colR];
    }

    // ---- neighbor exchange: v(4l-1) and v(4l+4) ----
    float vprev = __shfl_up_sync(0xffffffffu, v3, 1);
    float vnext = __shfl_down_sync(0xffffffffu, v0, 1);
    if (lane == 0)  vprev = vEL;
    if (lane == 31) vnext = vER;

    // ---- horizontal 4-tap: 2 outputs per lane ----
    float d0 = W0 * vprev + W1 * v0 + W2 * v1 + W3 * v2;
    float d1 = W0 * v1    + W1 * v2 + W2 * v3 + W3 * vnext;

    const int b = imgi / 3;
    const int c = imgi % 3;
    // out[t][b, q*3+c, i, j]  with tensor size 16*12*256*256
    float* p = out + ((size_t)(b * 12 + c) * 256 + i) * 256 + jb + 2 * lane;

#pragma unroll
    for (int t = 0; t < 4; t++) {
        float* pt = p + (size_t)t * (16 * 12 * 256 * 256);
#pragma unroll
        for (int q = 0; q < 4; q++) {
            float s = sc[t * 4 + q];
            float2 o = make_float2(s * d0, s * d1);
            __stcs((float2*)&pt[q * (3 * 256 * 256)], o);
        }
    }
}

extern "C" void kernel_launch(void* const* d_in, const int* in_sizes, int n_in,
                              void* d_out, int out_size) {
    const float* image = (const float*)d_in[0];
    const float* gl    = (const float*)d_in[1];
    const float* gh    = (const float*)d_in[2];
    const float* fl    = (const float*)d_in[3];
    const float* fh    = (const float*)d_in[4];
    float* out = (float*)d_out;

    dim3 block(256, 1, 1);
    dim3 grid(128, 48, 1);
    qwt_down_kernel<<<grid, block>>>(image, gl, gh, fl, fh, out);
}

// round 16
// speedup vs baseline: 1.0935x; 1.0608x over previous
#include <cuda_runtime.h>

// QWT collapses: filt(x,h) = x * sum(h) (scalar), downsample is linear.
// Every output sub-band = coef * D, D = bicubic stride-2 downsample of image.
// Inputs: image (16,3,512,512) f32, gl/gh/fl/fh (30 f32 each)
// Output: concat of 4 tensors, each (16,12,256,256) f32.
//
// NOTE: filter sums MUST be computed sequentially (k=0..29) — Σgh/Σfl/Σfh are
// cancellation sums ~0 whose fp32 value depends on summation order; keep the
// `#pragma unroll 1` loop (order-exact, reg-cheap).
//
// R15 (rerun; container infra failed twice, kernel never executed):
// R10 load structure (vertical pass fused into coalesced float4 global
// loads -> vrow smem, one barrier) + STG.128 fan-out stores (12cyc/16B vs
// STG.32's 20cyc/16B LSU issue) with an incrementally-stepped store pointer
// so the 16 far-apart addresses don't inflate register allocation (R2/R5
// lesson), and float4 LDS for the vrow reads (2-way vs 8-way conflicts).

#define W0 (-0.09375f)
#define W1 ( 0.59375f)
#define W2 ( 0.59375f)
#define W3 (-0.09375f)

#define TENSOR_STRIDE (16 * 12 * 256 * 256)   // floats per output tensor
#define Q_STRIDE      (3 * 256 * 256)         // floats per q step

// 256 threads/block: 4 output rows x 256 cols of one image.
// Grid: (64 row-groups, 48 images).
__global__ __launch_bounds__(256, 8) void qwt_down_kernel(const float* __restrict__ img,
                                                          const float* __restrict__ gl,
                                                          const float* __restrict__ gh,
                                                          const float* __restrict__ fl,
                                                          const float* __restrict__ fh,
                                                          float* __restrict__ out) {
    __shared__ __align__(16) float vrow[4][512];  // vertically-filtered rows
    __shared__ float sc[16];                      // 16 sub-band coefficients

    const int tid  = threadIdx.x;
    const int i0   = blockIdx.x * 4;   // first output row of this block
    const int imgi = blockIdx.y;       // b*3 + c

    // ---- threads 0..15: sequential (order-exact) filter sums + coefs ----
    if (tid < 16) {
        float A = 0.f, B = 0.f, C = 0.f, D = 0.f;
#pragma unroll 1
        for (int k = 0; k < 30; k++) {
            A += gl[k]; B += gh[k]; C += fl[k]; D += fh[k];
        }
        int t = tid >> 2, q = tid & 3;
        float f1 = (t < 2)        ? ((q & 1) ? C : A) : ((q & 1) ? D : B);
        float f2 = ((t & 1) == 0) ? ((q & 2) ? C : A) : ((q & 2) ? D : B);
        sc[tid] = f1 * f2;
    }

    const float* src = img + (size_t)imgi * 512 * 512;

    // ---- Stage V: vertical 4-tap pass fused with coalesced global loads ----
#pragma unroll
    for (int l = 0; l < 2; l++) {
        int idx = tid + l * 256;            // 0..511 (4 rows * 128 float4)
        int yy  = idx >> 7;                 // output row within block 0..3
        int c4  = (idx & 127) << 2;         // col base (coalesced per warp)
        int i   = i0 + yy;
        int rb  = 2 * i - 1;
        int r0  = max(0, rb);               // clamp top edge
        int r3  = min(511, rb + 3);         // clamp bottom edge
        float4 a = *(const float4*)&src[(size_t)r0 * 512 + c4];
        float4 b = *(const float4*)&src[(size_t)(rb + 1) * 512 + c4];
        float4 c = *(const float4*)&src[(size_t)(rb + 2) * 512 + c4];
        float4 d = *(const float4*)&src[(size_t)r3 * 512 + c4];
        float4 v;
        v.x = W0 * a.x + W1 * b.x + W2 * c.x + W3 * d.x;
        v.y = W0 * a.y + W1 * b.y + W2 * c.y + W3 * d.y;
        v.z = W0 * a.z + W1 * b.z + W2 * c.z + W3 * d.z;
        v.w = W0 * a.w + W1 * b.w + W2 * c.w + W3 * d.w;
        *(float4*)&vrow[yy][c4] = v;
    }
    __syncthreads();

    // ---- Stage H: horizontal pass, 4 consecutive outputs per thread ----
    const int x = tid & 63;                 // col group: outputs 4x..4x+3
    const int y = tid >> 6;                 // output row within block
    const int i = i0 + y;

    // cols 8x..8x+7 as two float4 LDS, plus clamped edge scalars
    float4 a0 = *(const float4*)&vrow[y][8 * x];
    float4 a1 = *(const float4*)&vrow[y][8 * x + 4];
    float vL = vrow[y][max(0, 8 * x - 1)];
    float vR = vrow[y][min(511, 8 * x + 8)];

    float d0 = W0 * vL   + W1 * a0.x + W2 * a0.y + W3 * a0.z;
    float d1 = W0 * a0.y + W1 * a0.z + W2 * a0.w + W3 * a1.x;
    float d2 = W0 * a0.w + W1 * a1.x + W2 * a1.y + W3 * a1.z;
    float d3 = W0 * a1.y + W1 * a1.z + W2 * a1.w + W3 * vR;

    const int b = imgi / 3;
    const int c = imgi % 3;
    // out[t][b, q*3+c, i, j]; walk one pointer through the 16 (t,q) slots
    float* p = out + ((size_t)(b * 12 + c) * 256 + i) * 256 + 4 * x;

#pragma unroll
    for (int t = 0; t < 4; t++) {
#pragma unroll
        for (int q = 0; q < 4; q++) {
            float s = sc[t * 4 + q];
            float4 o = make_float4(s * d0, s * d1, s * d2, s * d3);
            __stcs((float4*)p, o);
            p += Q_STRIDE;                       // constant step
        }
        p += TENSOR_STRIDE - 4 * Q_STRIDE;       // constant step
    }
}

extern "C" void kernel_launch(void* const* d_in, const int* in_sizes, int n_in,
                              void* d_out, int out_size) {
    const float* image = (const float*)d_in[0];
    const float* gl    = (const float*)d_in[1];
    const float* gh    = (const float*)d_in[2];
    const float* fl    = (const float*)d_in[3];
    const float* fh    = (const float*)d_in[4];
    float* out = (float*)d_out;

    dim3 block(256, 1, 1);
    dim3 grid(64, 48, 1);
    qwt_down_kernel<<<grid, block>>>(image, gl, gh, fl, fh, out);
}